// round 8
// baseline (speedup 1.0000x reference)
#include <cuda_runtime.h>

// Problem constants (fixed by the reference)
#define BB 4
#define DD 64
#define KK 32
#define NN 8192   // T*H*W = 8*32*32

// Scratch (no allocations allowed): tiny per-(b,d) vectors
__device__ float g_Eglob[BB * DD];
__device__ float g_gamma[BB * DD];

__device__ __forceinline__ float fast_ex2(float x) {
    float y;
    asm("ex2.approx.ftz.f32 %0, %1;" : "=f"(y) : "f"(x));
    return y;
}

// ---------------------------------------------------------------------------
// Kernel 1: E[b,d,n] = (sum_k e_k * r_k) / (sum_k e_k),
//           e_k = exp2( (scale[k,d]*log2e) * r_k^2 ),  r_k = x - cw[k,d]
// Grid: (NN/(4*256), B*D), block 256. Each thread: one float4 of n.
// ---------------------------------------------------------------------------
__global__ __launch_bounds__(256) void k_encode(
    const float* __restrict__ X,
    const float* __restrict__ cw,
    const float* __restrict__ sc,
    float* __restrict__ E)
{
    __shared__ float s_cw[KK];
    __shared__ float s_sc[KK];

    const int bd = blockIdx.y;            // b*DD + d
    const int d  = bd & (DD - 1);

    if (threadIdx.x < KK) {
        s_cw[threadIdx.x] = cw[threadIdx.x * DD + d];
        // fold log2(e) into the scale so exp() becomes a bare ex2
        s_sc[threadIdx.x] = sc[threadIdx.x * DD + d] * 1.4426950408889634f;
    }
    __syncthreads();

    const int n0 = (blockIdx.x * blockDim.x + threadIdx.x) * 4;
    const size_t base = (size_t)bd * NN + n0;
    const float4 x4 = *reinterpret_cast<const float4*>(X + base);

    float num0 = 0.f, num1 = 0.f, num2 = 0.f, num3 = 0.f;
    float den0 = 0.f, den1 = 0.f, den2 = 0.f, den3 = 0.f;

    #pragma unroll
    for (int k = 0; k < KK; k++) {
        const float c = s_cw[k];
        const float s = s_sc[k];
        const float r0 = x4.x - c;
        const float r1 = x4.y - c;
        const float r2 = x4.z - c;
        const float r3 = x4.w - c;
        const float e0 = fast_ex2(s * (r0 * r0));
        const float e1 = fast_ex2(s * (r1 * r1));
        const float e2 = fast_ex2(s * (r2 * r2));
        const float e3 = fast_ex2(s * (r3 * r3));
        den0 += e0; den1 += e1; den2 += e2; den3 += e3;
        num0 = fmaf(e0, r0, num0);
        num1 = fmaf(e1, r1, num1);
        num2 = fmaf(e2, r2, num2);
        num3 = fmaf(e3, r3, num3);
    }

    float4 o;
    o.x = num0 / den0;
    o.y = num1 / den1;
    o.z = num2 / den2;
    o.w = num3 / den3;
    *reinterpret_cast<float4*>(E + base) = o;
}

// ---------------------------------------------------------------------------
// Kernel 2: E_glob[b,d] = (1/K) * sum_n E[b,d,n]   (deterministic tree sum)
// Grid: B*D blocks, 256 threads.
// ---------------------------------------------------------------------------
__global__ __launch_bounds__(256) void k_reduce(const float* __restrict__ E)
{
    const int bd = blockIdx.x;
    const float* p = E + (size_t)bd * NN;

    float s = 0.f;
    #pragma unroll
    for (int i = threadIdx.x; i < NN; i += 256) s += p[i];

    #pragma unroll
    for (int o = 16; o > 0; o >>= 1)
        s += __shfl_xor_sync(0xffffffff, s, o);

    __shared__ float ws[8];
    if ((threadIdx.x & 31) == 0) ws[threadIdx.x >> 5] = s;
    __syncthreads();
    if (threadIdx.x == 0) {
        float t = 0.f;
        #pragma unroll
        for (int i = 0; i < 8; i++) t += ws[i];
        g_Eglob[bd] = t * (1.0f / KK);
    }
}

// ---------------------------------------------------------------------------
// Kernel 3: gamma[b,d] = sigmoid( sum_e Eglob[b,e]*fc_w[d,e] + fc_b[d] )
// One block of 256 threads (thread = b*DD + d).
// ---------------------------------------------------------------------------
__global__ __launch_bounds__(256) void k_gamma(
    const float* __restrict__ fw,
    const float* __restrict__ fb)
{
    const int t = threadIdx.x;       // b*DD + d
    const int b = t >> 6;
    const int d = t & (DD - 1);

    __shared__ float se[BB * DD];
    se[t] = g_Eglob[t];
    __syncthreads();

    float acc = fb[d];
    #pragma unroll
    for (int e = 0; e < DD; e++)
        acc = fmaf(se[b * DD + e], fw[d * DD + e], acc);

    // sigmoid
    g_gamma[t] = 1.0f / (1.0f + fast_ex2(-acc * 1.4426950408889634f));
}

// ---------------------------------------------------------------------------
// Kernel 4: out = relu(E * (1 + gamma[b,d]))  in-place on d_out, float4.
// Grid: (B*D*N)/(4*256) blocks of 256.
// ---------------------------------------------------------------------------
__global__ __launch_bounds__(256) void k_final(float* __restrict__ E)
{
    const int i  = blockIdx.x * blockDim.x + threadIdx.x;  // float4 index
    const int bd = i >> 11;                                // NN/4 = 2048 float4 per (b,d)
    const float g = 1.0f + g_gamma[bd];

    float4 v = reinterpret_cast<float4*>(E)[i];
    v.x = fmaxf(v.x * g, 0.0f);
    v.y = fmaxf(v.y * g, 0.0f);
    v.z = fmaxf(v.z * g, 0.0f);
    v.w = fmaxf(v.w * g, 0.0f);
    reinterpret_cast<float4*>(E)[i] = v;
}

// ---------------------------------------------------------------------------
extern "C" void kernel_launch(void* const* d_in, const int* in_sizes, int n_in,
                              void* d_out, int out_size)
{
    (void)in_sizes; (void)n_in; (void)out_size;
    const float* X  = (const float*)d_in[0];  // (B, D, T, H, W)
    const float* cw = (const float*)d_in[1];  // (K, D)
    const float* sc = (const float*)d_in[2];  // (K, D)
    const float* fw = (const float*)d_in[3];  // (D, D)
    const float* fb = (const float*)d_in[4];  // (D,)
    float* out = (float*)d_out;               // (B, D, T, H, W)

    dim3 g1(NN / (4 * 256), BB * DD);         // (8, 256)
    k_encode<<<g1, 256>>>(X, cw, sc, out);

    k_reduce<<<BB * DD, 256>>>(out);

    k_gamma<<<1, 256>>>(fw, fb);

    k_final<<<(BB * DD * NN) / (4 * 256), 256>>>(out);
}

// round 13
// speedup vs baseline: 1.4272x; 1.4272x over previous
#include <cuda_runtime.h>

// Problem constants (fixed by the reference)
#define BB 4
#define DD 64
#define KK 32
#define NN 8192        // T*H*W
#define GRID (BB*DD)   // 256 blocks, one per (b,d) row
#define TPB 256

typedef unsigned long long u64;

// Scratch + barrier state (no allocations allowed)
__device__ float    g_Eglob[BB * DD];
__device__ unsigned g_arrive;          // monotonic across graph replays

// ---- packed f32x2 helpers (sm_103a) --------------------------------------
__device__ __forceinline__ u64 pk2(float lo, float hi) {
    u64 r; asm("mov.b64 %0, {%1, %2};" : "=l"(r) : "f"(lo), "f"(hi)); return r;
}
__device__ __forceinline__ void up2(u64 v, float& lo, float& hi) {
    asm("mov.b64 {%0, %1}, %2;" : "=f"(lo), "=f"(hi) : "l"(v));
}
__device__ __forceinline__ u64 fma2_(u64 a, u64 b, u64 c) {
    u64 r; asm("fma.rn.f32x2 %0, %1, %2, %3;" : "=l"(r) : "l"(a), "l"(b), "l"(c)); return r;
}
__device__ __forceinline__ u64 add2_(u64 a, u64 b) {
    u64 r; asm("add.rn.f32x2 %0, %1, %2;" : "=l"(r) : "l"(a), "l"(b)); return r;
}
__device__ __forceinline__ float fex2(float x) {
    float y; asm("ex2.approx.ftz.f32 %0, %1;" : "=f"(y) : "f"(x)); return y;
}
__device__ __forceinline__ float frcp(float x) {
    float y; asm("rcp.approx.ftz.f32 %0, %1;" : "=f"(y) : "f"(x)); return y;
}
__device__ __forceinline__ u64 ex2_2(u64 a) {
    float lo, hi; up2(a, lo, hi);
    return pk2(fex2(lo), fex2(hi));
}

// ---------------------------------------------------------------------------
// One fused kernel. Phases:
//   1) encode:  E[b,d,n] = (Σ_k e_k (x-c_k)) / (Σ_k e_k),  e_k = 2^{A_k x^2 + B_k x + C_k}
//      E kept in registers; per-row sum reduced in-block -> g_Eglob[bd]
//   2) grid barrier (ticketed, replay-safe; co-residency guaranteed by
//      __launch_bounds__(256,2) with grid=256 <= 148*2)
//   3) gamma:   each block computes its own gamma[bd] from g_Eglob
//   4) out = relu(E * (1 + gamma)), single global write
// ---------------------------------------------------------------------------
__global__ __launch_bounds__(TPB, 2) void k_fused(
    const float* __restrict__ X,
    const float* __restrict__ cw,
    const float* __restrict__ sc,
    const float* __restrict__ fw,
    const float* __restrict__ fb,
    float* __restrict__ out)
{
    // per-k constants, pre-duplicated into f32x2 pairs: {A,B} and {C,c}
    __shared__ ulonglong2 sAB[KK];
    __shared__ ulonglong2 sCc[KK];
    __shared__ float s_eg[DD], s_fw[DD], s_red[8];
    __shared__ float s_gs;

    const int tid = threadIdx.x;
    const int bd  = blockIdx.x;          // b*DD + d
    const int d   = bd & (DD - 1);

    if (tid < KK) {
        const float s = sc[tid * DD + d] * 1.4426950408889634f;  // fold log2(e)
        const float c = cw[tid * DD + d];
        const float B = -2.0f * s * c;
        const float C = s * c * c;
        sAB[tid] = make_ulonglong2(pk2(s, s), pk2(B, B));
        sCc[tid] = make_ulonglong2(pk2(C, C), pk2(c, c));
    }
    __syncthreads();

    const size_t rowbase = (size_t)bd * NN;
    const float4* Xr = reinterpret_cast<const float4*>(X + rowbase);
    float4*       Or = reinterpret_cast<float4*>(out + rowbase);

    float4 ev[8];
    float  psum = 0.f;

    #pragma unroll
    for (int j = 0; j < 8; j++) {
        const float4 x4 = Xr[j * TPB + tid];
        const u64 xp0 = pk2(x4.x, x4.y);
        const u64 xp1 = pk2(x4.z, x4.w);
        u64 den0 = 0ull, den1 = 0ull;    // bit pattern == (0.f, 0.f)
        u64 cn0  = 0ull, cn1  = 0ull;

        #pragma unroll 8
        for (int k = 0; k < KK; k++) {
            const ulonglong2 ab = sAB[k];   // LDS.128 broadcast
            const ulonglong2 ccv = sCc[k];  // LDS.128 broadcast
            const u64 t0 = fma2_(ab.x, xp0, ab.y);
            const u64 a0 = fma2_(t0,  xp0, ccv.x);
            const u64 t1 = fma2_(ab.x, xp1, ab.y);
            const u64 a1 = fma2_(t1,  xp1, ccv.x);
            const u64 e0 = ex2_2(a0);
            const u64 e1 = ex2_2(a1);
            den0 = add2_(den0, e0);
            den1 = add2_(den1, e1);
            cn0  = fma2_(e0, ccv.y, cn0);
            cn1  = fma2_(e1, ccv.y, cn1);
        }

        float d0, d1, d2, d3, c0, c1, c2v, c3;
        up2(den0, d0, d1); up2(den1, d2, d3);
        up2(cn0,  c0, c1); up2(cn1,  c2v, c3);
        // num = x*den - cn  (algebraically == sum_k e_k (x - c_k))
        const float E0 = fmaf(x4.x, d0, -c0 ) * frcp(d0);
        const float E1 = fmaf(x4.y, d1, -c1 ) * frcp(d1);
        const float E2 = fmaf(x4.z, d2, -c2v) * frcp(d2);
        const float E3 = fmaf(x4.w, d3, -c3 ) * frcp(d3);
        ev[j] = make_float4(E0, E1, E2, E3);
        psum += (E0 + E1) + (E2 + E3);
    }

    // ---- block reduce psum -> g_Eglob[bd] (deterministic tree) ----
    #pragma unroll
    for (int o = 16; o > 0; o >>= 1)
        psum += __shfl_xor_sync(0xffffffffu, psum, o);
    if ((tid & 31) == 0) s_red[tid >> 5] = psum;
    __syncthreads();

    if (tid == 0) {
        float t = 0.f;
        #pragma unroll
        for (int i = 0; i < 8; i++) t += s_red[i];
        g_Eglob[bd] = t * (1.0f / KK);

        // ---- grid barrier (ticketed; monotonic counter is replay-safe) ----
        __threadfence();
        const unsigned ticket = atomicAdd(&g_arrive, 1u);
        const unsigned target = ticket - (ticket & (GRID - 1u)) + GRID;
        while ((int)(atomicAdd(&g_arrive, 0u) - target) < 0) { }
        __threadfence();
    }
    __syncthreads();

    // ---- gamma for this block's (b,d) ----
    if (tid < DD) {
        s_eg[tid] = __ldcg(&g_Eglob[(bd & ~(DD - 1)) + tid]);  // Eglob[b, :]
        s_fw[tid] = fw[d * DD + tid];                          // fc_w[d, :]
    }
    __syncthreads();
    if (tid == 0) {
        float acc = fb[d];
        #pragma unroll
        for (int e = 0; e < DD; e++)
            acc = fmaf(s_eg[e], s_fw[e], acc);
        // 1 + sigmoid(acc)
        s_gs = 1.0f + frcp(1.0f + fex2(-acc * 1.4426950408889634f));
    }
    __syncthreads();
    const float gs = s_gs;

    // ---- final: out = relu(E * (1 + gamma)) ----
    #pragma unroll
    for (int j = 0; j < 8; j++) {
        float4 v = ev[j];
        v.x = fmaxf(v.x * gs, 0.f);
        v.y = fmaxf(v.y * gs, 0.f);
        v.z = fmaxf(v.z * gs, 0.f);
        v.w = fmaxf(v.w * gs, 0.f);
        Or[j * TPB + tid] = v;
    }
}

// ---------------------------------------------------------------------------
extern "C" void kernel_launch(void* const* d_in, const int* in_sizes, int n_in,
                              void* d_out, int out_size)
{
    (void)in_sizes; (void)n_in; (void)out_size;
    const float* X  = (const float*)d_in[0];  // (B, D, T, H, W)
    const float* cw = (const float*)d_in[1];  // (K, D)
    const float* sc = (const float*)d_in[2];  // (K, D)
    const float* fw = (const float*)d_in[3];  // (D, D)
    const float* fb = (const float*)d_in[4];  // (D,)
    float* out = (float*)d_out;               // (B, D, T, H, W)

    k_fused<<<GRID, TPB>>>(X, cw, sc, fw, fb, out);
}